// round 1
// baseline (speedup 1.0000x reference)
#include <cuda_runtime.h>

// TraceRNN: T=512, B=32, F=256, L=8
// out = [ final_trace : B*F*L floats ][ ys : T*B*F*L floats ]
// ys[t, b, f*L + l], final_trace[b, f, l]

#define TT 512
#define BB 32
#define FF 256
#define LL 8

__global__ __launch_bounds__(64) void trace_rnn_kernel(
    const float* __restrict__ features,   // [T,B,F]
    const int*   __restrict__ resets,     // [T,B]
    const float* __restrict__ carry,      // [B,F,L]
    const float* __restrict__ lambdas,    // [L]
    float*       __restrict__ out)        // [B*F*L + T*B*F*L]
{
    __shared__ float snr[TT];             // (1 - reset[t, b]) as float

    const int bid = blockIdx.x;           // 128 blocks: 4 blocks per b
    const int b   = bid >> 2;
    const int f   = ((bid & 3) << 6) + threadIdx.x;
    const int bf  = b * FF + f;

    // Preload this b's resets into shared as nr = 1 - r
    for (int t = threadIdx.x; t < TT; t += 64) {
        snr[t] = (resets[t * BB + b] != 0) ? 0.0f : 1.0f;
    }
    __syncthreads();

    // Lambdas (broadcast, 8 scalars)
    float lam[LL];
#pragma unroll
    for (int l = 0; l < LL; ++l) lam[l] = __ldg(&lambdas[l]);

    // Trace accumulators from carry
    float tr[LL];
    {
        const float4* c = (const float4*)(carry + (size_t)bf * LL);
        float4 c0 = c[0], c1 = c[1];
        tr[0] = c0.x; tr[1] = c0.y; tr[2] = c0.z; tr[3] = c0.w;
        tr[4] = c1.x; tr[5] = c1.y; tr[6] = c1.z; tr[7] = c1.w;
    }

    const float* fptr = features + bf;              // stride B*F = 8192 per t
    float* yb = out + (size_t)BB * FF * LL + (size_t)bf * LL;  // ys base for this (b,f)

    // Software-pipelined feature loads, groups of 8 timesteps
    float fb[8];
#pragma unroll
    for (int u = 0; u < 8; ++u)
        fb[u] = __ldcs(fptr + (size_t)u * (BB * FF));

    for (int g = 0; g < TT / 8; ++g) {
        float fn[8];
        if (g < TT / 8 - 1) {
            const float* p = fptr + (size_t)(g + 1) * 8 * (BB * FF);
#pragma unroll
            for (int u = 0; u < 8; ++u)
                fn[u] = __ldcs(p + (size_t)u * (BB * FF));
        } else {
#pragma unroll
            for (int u = 0; u < 8; ++u) fn[u] = 0.0f;
        }

#pragma unroll
        for (int u = 0; u < 8; ++u) {
            const int t = g * 8 + u;
            const float fv = fb[u];
            const float nr = snr[t];
            // tr_l = r ? f : lam*tr + (1-lam)*f  ==  fma(lam*nr, tr - f, f)
#pragma unroll
            for (int l = 0; l < LL; ++l) {
                tr[l] = fmaf(lam[l] * nr, tr[l] - fv, fv);
            }
            float* yp = yb + (size_t)t * (BB * FF * LL);
            __stcs((float4*)yp,       make_float4(tr[0], tr[1], tr[2], tr[3]));
            __stcs((float4*)yp + 1,   make_float4(tr[4], tr[5], tr[6], tr[7]));
        }

#pragma unroll
        for (int u = 0; u < 8; ++u) fb[u] = fn[u];
    }

    // Final trace
    float4* ft = (float4*)(out + (size_t)bf * LL);
    ft[0] = make_float4(tr[0], tr[1], tr[2], tr[3]);
    ft[1] = make_float4(tr[4], tr[5], tr[6], tr[7]);
}

extern "C" void kernel_launch(void* const* d_in, const int* in_sizes, int n_in,
                              void* d_out, int out_size) {
    const float* features = (const float*)d_in[0];
    const int*   resets   = (const int*)d_in[1];
    const float* carry    = (const float*)d_in[2];
    const float* lambdas  = (const float*)d_in[3];
    float* out = (float*)d_out;

    // grid: 4 blocks per batch row, 64 threads each -> one thread per (b,f)
    trace_rnn_kernel<<<(BB * FF) / 64, 64>>>(features, resets, carry, lambdas, out);
}

// round 2
// speedup vs baseline: 1.0302x; 1.0302x over previous
#include <cuda_runtime.h>

// TraceRNN: T=512, B=32, F=256, L=8
// out = [ final_trace : B*F*L floats ][ ys : T*B*F*L floats ]
// One thread per (b, f, l): 65536 threads total.

#define TT 512
#define BB 32
#define FF 256
#define LL 8
#define BFL (BB * FF * LL)   // 65536, ys stride per timestep
#define BF  (BB * FF)        // 8192, features stride per timestep

__global__ __launch_bounds__(256) void trace_rnn_kernel(
    const float* __restrict__ features,   // [T,B,F]
    const int*   __restrict__ resets,     // [T,B]
    const float* __restrict__ carry,      // [B,F,L]
    const float* __restrict__ lambdas,    // [L]
    float*       __restrict__ out)        // [BFL + T*BFL]
{
    __shared__ float snr[TT];             // (1 - reset[t, b]) as float

    const int g = blockIdx.x * 256 + threadIdx.x;   // (b,f,l) flat index
    const int b = blockIdx.x >> 3;                  // 2048 threads per b, 8 blocks per b
    const int l = g & 7;

    // Preload this b's resets into shared as nr = 1 - r
    for (int t = threadIdx.x; t < TT; t += 256) {
        snr[t] = (resets[t * BB + b] != 0) ? 0.0f : 1.0f;
    }
    __syncthreads();

    const float lam = __ldg(&lambdas[l]);
    float tr = __ldg(&carry[g]);

    const float* fptr = features + (g >> 3);   // stride BF per timestep
    float* yb = out + (size_t)BFL + g;         // ys base, stride BFL per timestep

    // Software-pipelined feature loads, groups of 8 timesteps
    float fb[8];
#pragma unroll
    for (int u = 0; u < 8; ++u)
        fb[u] = __ldcs(fptr + (size_t)u * BF);

    for (int gi = 0; gi < TT / 8; ++gi) {
        float fn[8];
        if (gi < TT / 8 - 1) {
            const float* p = fptr + (size_t)(gi + 1) * 8 * BF;
#pragma unroll
            for (int u = 0; u < 8; ++u)
                fn[u] = __ldcs(p + (size_t)u * BF);
        }

#pragma unroll
        for (int u = 0; u < 8; ++u) {
            const int t = gi * 8 + u;
            const float fv = fb[u];
            const float nr = snr[t];
            // tr = r ? f : lam*tr + (1-lam)*f  ==  fma(lam*nr, tr - fv, fv)
            tr = fmaf(lam * nr, tr - fv, fv);
            __stcs(yb + (size_t)t * BFL, tr);
        }

#pragma unroll
        for (int u = 0; u < 8; ++u) fb[u] = fn[u];
    }

    // Final trace
    out[g] = tr;
}

extern "C" void kernel_launch(void* const* d_in, const int* in_sizes, int n_in,
                              void* d_out, int out_size) {
    const float* features = (const float*)d_in[0];
    const int*   resets   = (const int*)d_in[1];
    const float* carry    = (const float*)d_in[2];
    const float* lambdas  = (const float*)d_in[3];
    float* out = (float*)d_out;

    trace_rnn_kernel<<<BFL / 256, 256>>>(features, resets, carry, lambdas, out);
}

// round 3
// speedup vs baseline: 1.5259x; 1.4812x over previous
#include <cuda_runtime.h>

// TraceRNN: T=512, B=32, F=256, L=8
// out = [ final_trace : B*F*L ][ ys : T*B*F*L ]
// Chunked affine scan: C=8 chunks of 64 timesteps.
// Thread granularity: one (b, f, lambda-quad) per thread; 2 quads per (b,f).

#define TT  512
#define BB  32
#define FF  256
#define LL  8
#define BF  (BB * FF)        // 8192
#define BFL (BB * FF * LL)   // 65536
#define QQ  (BFL / 4)        // 16384 lambda-quads
#define CC  8                // chunks
#define CL  (TT / CC)        // 64 steps per chunk

// Scratch (device globals; no allocation allowed)
__device__ float4 g_Pend[CC][QQ];   // chunk-end trace with zero init
__device__ float4 g_A[CC][QQ];      // product of a_t over chunk
__device__ float4 g_init[CC][QQ];   // exact init trace for each chunk

// ---------------------------------------------------------------- K1 ----
__global__ __launch_bounds__(256) void k1_summary(
    const float* __restrict__ features,
    const int*   __restrict__ resets,
    const float* __restrict__ lambdas)
{
    __shared__ float snr[CL];
    const int c  = blockIdx.y;
    const int q  = blockIdx.x * 256 + threadIdx.x;
    const int b  = q >> 9;                 // 512 quads per b
    const int t0 = c * CL;

    for (int i = threadIdx.x; i < CL; i += 256)
        snr[i] = (resets[(t0 + i) * BB + b] != 0) ? 0.0f : 1.0f;
    __syncthreads();

    const int l0 = (q & 1) * 4;
    const float lam0 = __ldg(&lambdas[l0 + 0]);
    const float lam1 = __ldg(&lambdas[l0 + 1]);
    const float lam2 = __ldg(&lambdas[l0 + 2]);
    const float lam3 = __ldg(&lambdas[l0 + 3]);

    float t0v = 0.f, t1v = 0.f, t2v = 0.f, t3v = 0.f;
    float pn = 1.0f;                        // product of nr over chunk (0 or 1)

    const float* fp = features + (size_t)t0 * BF + (q >> 1);

#pragma unroll 8
    for (int i = 0; i < CL; ++i) {
        const float fv = __ldcg(fp + (size_t)i * BF);
        const float nr = snr[i];
        pn = fminf(pn, nr);
        t0v = fmaf(lam0 * nr, t0v - fv, fv);
        t1v = fmaf(lam1 * nr, t1v - fv, fv);
        t2v = fmaf(lam2 * nr, t2v - fv, fv);
        t3v = fmaf(lam3 * nr, t3v - fv, fv);
    }

    // A_l = lam_l^64 * pn   (6 squarings)
    float a0 = lam0, a1 = lam1, a2 = lam2, a3 = lam3;
#pragma unroll
    for (int s = 0; s < 6; ++s) { a0 *= a0; a1 *= a1; a2 *= a2; a3 *= a3; }

    g_Pend[c][q] = make_float4(t0v, t1v, t2v, t3v);
    g_A[c][q]    = make_float4(a0 * pn, a1 * pn, a2 * pn, a3 * pn);
}

// --------------------------------------------------------------- K2a ----
__global__ __launch_bounds__(256) void k2a_fixup(const float* __restrict__ carry)
{
    const int q = blockIdx.x * 256 + threadIdx.x;
    float4 cur = ((const float4*)carry)[q];
#pragma unroll
    for (int c = 0; c < CC; ++c) {
        g_init[c][q] = cur;
        const float4 P = g_Pend[c][q];
        const float4 A = g_A[c][q];
        cur.x = fmaf(A.x, cur.x, P.x);
        cur.y = fmaf(A.y, cur.y, P.y);
        cur.z = fmaf(A.z, cur.z, P.z);
        cur.w = fmaf(A.w, cur.w, P.w);
    }
}

// ---------------------------------------------------------------- K2 ----
__global__ __launch_bounds__(256) void k2_emit(
    const float* __restrict__ features,
    const int*   __restrict__ resets,
    const float* __restrict__ lambdas,
    float*       __restrict__ out)
{
    __shared__ float snr[CL];
    const int c  = blockIdx.y;
    const int q  = blockIdx.x * 256 + threadIdx.x;
    const int b  = q >> 9;
    const int t0 = c * CL;

    for (int i = threadIdx.x; i < CL; i += 256)
        snr[i] = (resets[(t0 + i) * BB + b] != 0) ? 0.0f : 1.0f;
    __syncthreads();

    const int l0 = (q & 1) * 4;
    const float lam0 = __ldg(&lambdas[l0 + 0]);
    const float lam1 = __ldg(&lambdas[l0 + 1]);
    const float lam2 = __ldg(&lambdas[l0 + 2]);
    const float lam3 = __ldg(&lambdas[l0 + 3]);

    float4 tr = g_init[c][q];

    const float* fp = features + (size_t)t0 * BF + (q >> 1);
    float* yb = out + (size_t)BFL + (size_t)t0 * BFL + (size_t)q * 4;

    // Pipelined feature loads, groups of 8
    float fb[8];
#pragma unroll
    for (int u = 0; u < 8; ++u)
        fb[u] = __ldcg(fp + (size_t)u * BF);

    for (int gi = 0; gi < CL / 8; ++gi) {
        float fn[8];
        if (gi < CL / 8 - 1) {
            const float* p = fp + (size_t)(gi + 1) * 8 * BF;
#pragma unroll
            for (int u = 0; u < 8; ++u)
                fn[u] = __ldcg(p + (size_t)u * BF);
        }

#pragma unroll
        for (int u = 0; u < 8; ++u) {
            const int i = gi * 8 + u;
            const float fv = fb[u];
            const float nr = snr[i];
            tr.x = fmaf(lam0 * nr, tr.x - fv, fv);
            tr.y = fmaf(lam1 * nr, tr.y - fv, fv);
            tr.z = fmaf(lam2 * nr, tr.z - fv, fv);
            tr.w = fmaf(lam3 * nr, tr.w - fv, fv);
            __stcs((float4*)(yb + (size_t)i * BFL), tr);
        }

#pragma unroll
        for (int u = 0; u < 8; ++u) fb[u] = fn[u];
    }

    if (c == CC - 1)
        ((float4*)out)[q] = tr;   // final trace
}

// ------------------------------------------------------------- launch ----
extern "C" void kernel_launch(void* const* d_in, const int* in_sizes, int n_in,
                              void* d_out, int out_size) {
    const float* features = (const float*)d_in[0];
    const int*   resets   = (const int*)d_in[1];
    const float* carry    = (const float*)d_in[2];
    const float* lambdas  = (const float*)d_in[3];
    float* out = (float*)d_out;

    dim3 grid(QQ / 256, CC);
    k1_summary<<<grid, 256>>>(features, resets, lambdas);
    k2a_fixup<<<QQ / 256, 256>>>(carry);
    k2_emit<<<grid, 256>>>(features, resets, lambdas, out);
}

// round 4
// speedup vs baseline: 1.9570x; 1.2825x over previous
#include <cuda_runtime.h>

// TraceRNN: T=512, B=32, F=256, L=8
// out = [ final_trace : B*F*L ][ ys : T*B*F*L ]
// Single fused kernel: C=16 chunks of 32 steps; block = 16 quads x 16 chunks.
// Phase 1: per-thread chunk summary (P, A) -> smem
// Phase 2: block-local affine scan -> exact chunk init
// Phase 3: re-run chunk from exact init, stream ys (features re-read hits L1)

#define TT  512
#define BB  32
#define FF  256
#define LL  8
#define BF  (BB * FF)        // 8192
#define BFL (BB * FF * LL)   // 65536
#define QQ  (BFL / 4)        // 16384 lambda-quads
#define CC  16               // chunks
#define CL  (TT / CC)        // 32 steps per chunk
#define QPB 16               // quads per block
#define NT  256              // QPB * CC

__global__ __launch_bounds__(NT) void trace_fused(
    const float* __restrict__ features,   // [T,B,F]
    const int*   __restrict__ resets,     // [T,B]
    const float* __restrict__ carry,      // [B,F,L]
    const float* __restrict__ lambdas,    // [L]
    float*       __restrict__ out)        // [BFL + T*BFL]
{
    __shared__ float  snr[TT];            // (1 - reset[t,b]), 2 KB
    __shared__ float4 sP[CC][QPB];        // chunk-end trace (init 0), 4 KB
    __shared__ float4 sA[CC][QPB];        // chunk decay product,      4 KB

    const int tid = threadIdx.x;
    const int ql  = tid & (QPB - 1);      // quad within block
    const int c   = tid >> 4;             // chunk index 0..15
    const int q   = blockIdx.x * QPB + ql;
    const int b   = q >> 9;               // 512 quads per batch row
    const int col = q >> 1;               // = b*FF + f
    const int t0  = c * CL;

    // ---- resets -> smem (whole T range, shared by all chunks) ----
    for (int i = tid; i < TT; i += NT)
        snr[i] = (resets[i * BB + b] != 0) ? 0.0f : 1.0f;

    const int   l0   = (q & 1) * 4;
    const float lam0 = __ldg(&lambdas[l0 + 0]);
    const float lam1 = __ldg(&lambdas[l0 + 1]);
    const float lam2 = __ldg(&lambdas[l0 + 2]);
    const float lam3 = __ldg(&lambdas[l0 + 3]);

    const float* fp = features + (size_t)t0 * BF + col;

    // Issue first feature group before the barrier (independent of snr)
    float fb[8];
#pragma unroll
    for (int u = 0; u < 8; ++u)
        fb[u] = fp[(size_t)u * BF];

    __syncthreads();

    // ---- Phase 1: chunk summary with zero init ----
    float s0 = 0.f, s1 = 0.f, s2 = 0.f, s3 = 0.f, pn = 1.0f;

#pragma unroll
    for (int g = 0; g < CL / 8; ++g) {
        float fn[8];
        if (g < CL / 8 - 1) {
            const float* p = fp + (size_t)(g + 1) * 8 * BF;
#pragma unroll
            for (int u = 0; u < 8; ++u)
                fn[u] = p[(size_t)u * BF];
        }
#pragma unroll
        for (int u = 0; u < 8; ++u) {
            const float fv = fb[u];
            const float nr = snr[t0 + g * 8 + u];
            pn = fminf(pn, nr);
            s0 = fmaf(lam0 * nr, s0 - fv, fv);
            s1 = fmaf(lam1 * nr, s1 - fv, fv);
            s2 = fmaf(lam2 * nr, s2 - fv, fv);
            s3 = fmaf(lam3 * nr, s3 - fv, fv);
        }
#pragma unroll
        for (int u = 0; u < 8; ++u) fb[u] = fn[u];
    }

    // A_l = lam^32 * pn  (5 squarings)
    float a0 = lam0, a1 = lam1, a2 = lam2, a3 = lam3;
#pragma unroll
    for (int s = 0; s < 5; ++s) { a0 *= a0; a1 *= a1; a2 *= a2; a3 *= a3; }

    sP[c][ql] = make_float4(s0, s1, s2, s3);
    sA[c][ql] = make_float4(a0 * pn, a1 * pn, a2 * pn, a3 * pn);
    __syncthreads();

    // ---- Phase 2: fold exact init for this chunk ----
    float4 tr = ((const float4*)carry)[q];
    for (int j = 0; j < c; ++j) {
        const float4 P = sP[j][ql];
        const float4 A = sA[j][ql];
        tr.x = fmaf(A.x, tr.x, P.x);
        tr.y = fmaf(A.y, tr.y, P.y);
        tr.z = fmaf(A.z, tr.z, P.z);
        tr.w = fmaf(A.w, tr.w, P.w);
    }

    // ---- Phase 3: emit (feature re-read hits L1) ----
    float* yb = out + (size_t)BFL + (size_t)t0 * BFL + (size_t)q * 4;

#pragma unroll
    for (int u = 0; u < 8; ++u)
        fb[u] = fp[(size_t)u * BF];

#pragma unroll
    for (int g = 0; g < CL / 8; ++g) {
        float fn[8];
        if (g < CL / 8 - 1) {
            const float* p = fp + (size_t)(g + 1) * 8 * BF;
#pragma unroll
            for (int u = 0; u < 8; ++u)
                fn[u] = p[(size_t)u * BF];
        }
#pragma unroll
        for (int u = 0; u < 8; ++u) {
            const int   i  = g * 8 + u;
            const float fv = fb[u];
            const float nr = snr[t0 + i];
            tr.x = fmaf(lam0 * nr, tr.x - fv, fv);
            tr.y = fmaf(lam1 * nr, tr.y - fv, fv);
            tr.z = fmaf(lam2 * nr, tr.z - fv, fv);
            tr.w = fmaf(lam3 * nr, tr.w - fv, fv);
            __stcs((float4*)(yb + (size_t)i * BFL), tr);
        }
#pragma unroll
        for (int u = 0; u < 8; ++u) fb[u] = fn[u];
    }

    if (c == CC - 1)
        ((float4*)out)[q] = tr;   // final trace
}

extern "C" void kernel_launch(void* const* d_in, const int* in_sizes, int n_in,
                              void* d_out, int out_size) {
    const float* features = (const float*)d_in[0];
    const int*   resets   = (const int*)d_in[1];
    const float* carry    = (const float*)d_in[2];
    const float* lambdas  = (const float*)d_in[3];
    float* out = (float*)d_out;

    trace_fused<<<QQ / QPB, NT>>>(features, resets, carry, lambdas, out);
}